// round 1
// baseline (speedup 1.0000x reference)
#include <cuda_runtime.h>

#define IMH 512
#define IMW 512
#define TX 32
#define TY 8
#define PITCH 41            // 40 halo-padded columns + 1 pad (bank decorrelation)
#define NROWS 16            // TY + 8
#define PLANE (PITCH * NROWS)

__device__ __forceinline__ void ce(float& a, float& b) {
    float lo = fminf(a, b);
    float hi = fmaxf(a, b);
    a = lo;
    b = hi;
}

// Exact median of the 9x9 window whose top-left element is smem[base],
// row stride PITCH. Forgetful selection: 42-register buffer, drop min&max,
// insert next, shrink. All indices constant after full unroll -> registers.
__device__ __noinline__ float median81(int base) {
    extern __shared__ float smem[];
    float b[42];
#pragma unroll
    for (int i = 0; i < 42; i++)
        b[i] = smem[base + (i / 9) * PITCH + (i % 9)];

#pragma unroll
    for (int i = 42; i < 81; i++) {
        const int m = 84 - i;  // active buffer size: 42 down to 4
        // min tree -> b[0] (multiset-preserving compare-exchange tree)
#pragma unroll
        for (int s = 1; s < m; s <<= 1) {
#pragma unroll
            for (int j = 0; j + s < m; j += 2 * s) ce(b[j], b[j + s]);
        }
        // max tree over b[1..m-1] -> b[m-1]
#pragma unroll
        for (int s = 1; s < m - 1; s <<= 1) {
#pragma unroll
            for (int j = m - 1; j - s >= 1; j -= 2 * s) ce(b[j - s], b[j]);
        }
        // discard min (overwrite) and max (excluded by shrink next iter)
        b[0] = smem[base + (i / 9) * PITCH + (i % 9)];
    }
    // 3 survivors: median is the middle one
    ce(b[0], b[1]); ce(b[1], b[2]); ce(b[0], b[1]);
    return b[1];
}

__device__ __forceinline__ int reflect_idx(int i, int n) {
    if (i < 0) i = -1 - i;          // numpy 'symmetric' padding
    if (i >= n) i = 2 * n - 1 - i;
    return i;
}

__global__ void __launch_bounds__(256)
denoise_median_kernel(const float* __restrict__ img, float* __restrict__ out) {
    extern __shared__ float smem[];
    float* sY = smem;
    float* sU = smem + PLANE;
    float* sV = smem + 2 * PLANE;

    const int bx = blockIdx.x * TX;
    const int by = blockIdx.y * TY;
    const int bat = blockIdx.z;
    const int tid = threadIdx.x;

    const float* Rp = img + (size_t)bat * 3 * IMH * IMW;
    const float* Gp = Rp + IMH * IMW;
    const float* Bp = Gp + IMH * IMW;

    // Load halo tile (40 x 16 logical), RGB->YUV on the fly
    for (int idx = tid; idx < NROWS * 40; idx += 256) {
        int r = idx / 40;
        int c = idx % 40;
        int gy = reflect_idx(by - 4 + r, IMH);
        int gx = reflect_idx(bx - 4 + c, IMW);
        float R = Rp[gy * IMW + gx];
        float G = Gp[gy * IMW + gx];
        float B = Bp[gy * IMW + gx];
        sY[r * PITCH + c] = 0.299f * R + 0.587f * G + 0.114f * B;
        sU[r * PITCH + c] = -0.14713f * R - 0.28886f * G + 0.436f * B;
        sV[r * PITCH + c] = 0.615f * R - 0.51499f * G - 0.10001f * B;
    }
    __syncthreads();

    const int tx = tid & 31;
    const int ty = tid >> 5;

    // ---- Luma: 3x3 median (19-CE network), then clip to [0,1] ----
    float p[9];
#pragma unroll
    for (int k = 0; k < 9; k++)
        p[k] = sY[(ty + 3 + k / 3) * PITCH + (tx + 3 + k % 3)];

    ce(p[1], p[2]); ce(p[4], p[5]); ce(p[7], p[8]);
    ce(p[0], p[1]); ce(p[3], p[4]); ce(p[6], p[7]);
    ce(p[1], p[2]); ce(p[4], p[5]); ce(p[7], p[8]);
    ce(p[0], p[3]); ce(p[5], p[8]); ce(p[4], p[7]);
    ce(p[3], p[6]); ce(p[1], p[4]); ce(p[2], p[5]);
    ce(p[4], p[7]); ce(p[4], p[2]); ce(p[6], p[4]);
    ce(p[4], p[2]);
    float ylum = fminf(fmaxf(p[4], 0.0f), 1.0f);

    // ---- Chroma: exact 9x9 medians ----
    float u = median81(PLANE + ty * PITCH + tx);
    float v = median81(2 * PLANE + ty * PITCH + tx);

    // ---- YUV -> RGB ----
    float R = ylum + 1.13983f * v;
    float G = ylum - 0.39465f * u - 0.5806f * v;
    float B = ylum + 2.03211f * u;

    const int gy = by + ty;
    const int gx = bx + tx;
    size_t o = (size_t)bat * 3 * IMH * IMW + (size_t)gy * IMW + gx;
    out[o] = R;
    out[o + IMH * IMW] = G;
    out[o + 2 * IMH * IMW] = B;
}

extern "C" void kernel_launch(void* const* d_in, const int* in_sizes, int n_in,
                              void* d_out, int out_size) {
    const float* img = (const float*)d_in[0];
    float* out = (float*)d_out;
    int batch = in_sizes[0] / (3 * IMH * IMW);
    dim3 grid(IMW / TX, IMH / TY, batch);
    size_t smem_bytes = 3 * PLANE * sizeof(float);
    denoise_median_kernel<<<grid, 256, smem_bytes>>>(img, out);
}

// round 2
// speedup vs baseline: 2.1114x; 2.1114x over previous
#include <cuda_runtime.h>
#include <cuda_fp16.h>

#define IMH 512
#define IMW 512
#define TX 32
#define TY 8
#define PITCH 41            // 40 halo-padded columns + 1 pad
#define NROWS 16            // TY + 8
#define PLANE (PITCH * NROWS)

__device__ __forceinline__ void ce(float& a, float& b) {
    float lo = fminf(a, b);
    float hi = fmaxf(a, b);
    a = lo;
    b = hi;
}

__device__ __forceinline__ void ce2(__half2& a, __half2& b) {
    __half2 lo = __hmin2(a, b);
    __half2 hi = __hmax2(a, b);
    a = lo;
    b = hi;
}

// Exact median of the 9x9 window over a half2 (U,V packed) smem plane.
// Forgetful selection: 42-register buffer, full min tree + max tree per step.
// Both half-lanes get their medians simultaneously.
__device__ __forceinline__ __half2 median81_h2(const __half2* __restrict__ sUV, int base) {
    __half2 b[42];
#pragma unroll
    for (int i = 0; i < 42; i++)
        b[i] = sUV[base + (i / 9) * PITCH + (i % 9)];

#pragma unroll
    for (int i = 42; i < 81; i++) {
        const int m = 84 - i;  // active buffer size: 42 down to 4
        // min tree -> b[0]
#pragma unroll
        for (int s = 1; s < m; s <<= 1) {
#pragma unroll
            for (int j = 0; j + s < m; j += 2 * s) ce2(b[j], b[j + s]);
        }
        // max tree over b[1..m-1] -> b[m-1]
#pragma unroll
        for (int s = 1; s < m - 1; s <<= 1) {
#pragma unroll
            for (int j = m - 1; j - s >= 1; j -= 2 * s) ce2(b[j - s], b[j]);
        }
        // discard min (overwrite) and max (excluded by shrink next iter)
        b[0] = sUV[base + (i / 9) * PITCH + (i % 9)];
    }
    ce2(b[0], b[1]); ce2(b[1], b[2]); ce2(b[0], b[1]);
    return b[1];
}

__device__ __forceinline__ int reflect_idx(int i, int n) {
    if (i < 0) i = -1 - i;          // numpy 'symmetric' padding
    if (i >= n) i = 2 * n - 1 - i;
    return i;
}

__global__ void __launch_bounds__(256, 2)
denoise_median_kernel(const float* __restrict__ img, float* __restrict__ out) {
    __shared__ float sY[PLANE];
    __shared__ __half2 sUV[PLANE];

    const int bx = blockIdx.x * TX;
    const int by = blockIdx.y * TY;
    const int bat = blockIdx.z;
    const int tid = threadIdx.x;

    const float* Rp = img + (size_t)bat * 3 * IMH * IMW;
    const float* Gp = Rp + IMH * IMW;
    const float* Bp = Gp + IMH * IMW;

    // Load halo tile (40 x 16 logical), RGB->YUV on the fly.
    for (int idx = tid; idx < NROWS * 40; idx += 256) {
        int r = idx / 40;
        int c = idx % 40;
        int gy = reflect_idx(by - 4 + r, IMH);
        int gx = reflect_idx(bx - 4 + c, IMW);
        float R = Rp[gy * IMW + gx];
        float G = Gp[gy * IMW + gx];
        float B = Bp[gy * IMW + gx];
        float Y = 0.299f * R + 0.587f * G + 0.114f * B;
        float U = -0.14713f * R - 0.28886f * G + 0.436f * B;
        float V = 0.615f * R - 0.51499f * G - 0.10001f * B;
        sY[r * PITCH + c] = Y;
        sUV[r * PITCH + c] = __floats2half2_rn(U, V);
    }
    __syncthreads();

    const int tx = tid & 31;
    const int ty = tid >> 5;

    // ---- Luma: 3x3 median (19-CE network, fp32), then clip to [0,1] ----
    float p[9];
#pragma unroll
    for (int k = 0; k < 9; k++)
        p[k] = sY[(ty + 3 + k / 3) * PITCH + (tx + 3 + k % 3)];

    ce(p[1], p[2]); ce(p[4], p[5]); ce(p[7], p[8]);
    ce(p[0], p[1]); ce(p[3], p[4]); ce(p[6], p[7]);
    ce(p[1], p[2]); ce(p[4], p[5]); ce(p[7], p[8]);
    ce(p[0], p[3]); ce(p[5], p[8]); ce(p[4], p[7]);
    ce(p[3], p[6]); ce(p[1], p[4]); ce(p[2], p[5]);
    ce(p[4], p[7]); ce(p[4], p[2]); ce(p[6], p[4]);
    ce(p[4], p[2]);
    float ylum = fminf(fmaxf(p[4], 0.0f), 1.0f);

    // ---- Chroma: exact 9x9 medians of U and V simultaneously (half2) ----
    __half2 uv = median81_h2(sUV, ty * PITCH + tx);
    float u = __low2float(uv);
    float v = __high2float(uv);

    // ---- YUV -> RGB ----
    float R = ylum + 1.13983f * v;
    float G = ylum - 0.39465f * u - 0.5806f * v;
    float B = ylum + 2.03211f * u;

    const int gy = by + ty;
    const int gx = bx + tx;
    size_t o = (size_t)bat * 3 * IMH * IMW + (size_t)gy * IMW + gx;
    out[o] = R;
    out[o + IMH * IMW] = G;
    out[o + 2 * IMH * IMW] = B;
}

extern "C" void kernel_launch(void* const* d_in, const int* in_sizes, int n_in,
                              void* d_out, int out_size) {
    const float* img = (const float*)d_in[0];
    float* out = (float*)d_out;
    int batch = in_sizes[0] / (3 * IMH * IMW);
    dim3 grid(IMW / TX, IMH / TY, batch);
    denoise_median_kernel<<<grid, 256>>>(img, out);
}

// round 3
// speedup vs baseline: 13.9615x; 6.6124x over previous
#include <cuda_runtime.h>
#include <cuda_fp16.h>

#define IMH 512
#define IMW 512
#define TX 32
#define TY 8
#define PITCH 41            // 40 halo-padded columns + 1 pad
#define NROWS 16            // TY + 8
#define PLANE (PITCH * NROWS)

__device__ __forceinline__ void ce(float& a, float& b) {
    float lo = fminf(a, b);
    float hi = fmaxf(a, b);
    a = lo;
    b = hi;
}

__device__ __forceinline__ void ce2(__half2& a, __half2& b) {
    __half2 lo = __hmin2(a, b);
    __half2 hi = __hmax2(a, b);
    a = lo;
    b = hi;
}

// Min tournament over b[0..M): min lands in b[0]. Multiset-preserving.
template <int M>
__device__ __forceinline__ void min_tree(__half2 (&b)[42]) {
#pragma unroll
    for (int s = 1; s < M; s <<= 1) {
#pragma unroll
        for (int j = 0; j + s < M; j += 2 * s) ce2(b[j], b[j + s]);
    }
}

// Max tournament over b[1..M): max lands in b[M-1].
template <int M>
__device__ __forceinline__ void max_tree(__half2 (&b)[42]) {
#pragma unroll
    for (int s = 1; s < M - 1; s <<= 1) {
#pragma unroll
        for (int j = M - 1; j - s >= 1; j -= 2 * s) ce2(b[j - s], b[j]);
    }
}

// Forget steps I = 42..80, active size M = 84-I. Template recursion forces
// full unrolling: every b[] index is a compile-time constant -> registers.
template <int I>
__device__ __forceinline__ void forget_steps(__half2 (&b)[42],
                                             const __half2* __restrict__ sUV,
                                             int base) {
    if constexpr (I < 81) {
        constexpr int M = 84 - I;
        min_tree<M>(b);   // discard min (overwritten below)
        max_tree<M>(b);   // discard max (excluded by shrink)
        b[0] = sUV[base + (I / 9) * PITCH + (I % 9)];
        forget_steps<I + 1>(b, sUV, base);
    }
}

__device__ __forceinline__ __half2 median81_h2(const __half2* __restrict__ sUV, int base) {
    __half2 b[42];
#pragma unroll
    for (int i = 0; i < 42; i++)
        b[i] = sUV[base + (i / 9) * PITCH + (i % 9)];

    forget_steps<42>(b, sUV, base);

    // 3 survivors: median is the middle one
    ce2(b[0], b[1]); ce2(b[1], b[2]); ce2(b[0], b[1]);
    return b[1];
}

__device__ __forceinline__ int reflect_idx(int i, int n) {
    if (i < 0) i = -1 - i;          // numpy 'symmetric' padding
    if (i >= n) i = 2 * n - 1 - i;
    return i;
}

__global__ void __launch_bounds__(256, 2)
denoise_median_kernel(const float* __restrict__ img, float* __restrict__ out) {
    __shared__ float sY[PLANE];
    __shared__ __half2 sUV[PLANE];

    const int bx = blockIdx.x * TX;
    const int by = blockIdx.y * TY;
    const int bat = blockIdx.z;
    const int tid = threadIdx.x;

    const float* Rp = img + (size_t)bat * 3 * IMH * IMW;
    const float* Gp = Rp + IMH * IMW;
    const float* Bp = Gp + IMH * IMW;

    // Load halo tile (40 x 16 logical), RGB->YUV on the fly.
    for (int idx = tid; idx < NROWS * 40; idx += 256) {
        int r = idx / 40;
        int c = idx % 40;
        int gy = reflect_idx(by - 4 + r, IMH);
        int gx = reflect_idx(bx - 4 + c, IMW);
        float R = Rp[gy * IMW + gx];
        float G = Gp[gy * IMW + gx];
        float B = Bp[gy * IMW + gx];
        float Y = 0.299f * R + 0.587f * G + 0.114f * B;
        float U = -0.14713f * R - 0.28886f * G + 0.436f * B;
        float V = 0.615f * R - 0.51499f * G - 0.10001f * B;
        sY[r * PITCH + c] = Y;
        sUV[r * PITCH + c] = __floats2half2_rn(U, V);
    }
    __syncthreads();

    const int tx = tid & 31;
    const int ty = tid >> 5;

    // ---- Luma first (its 9 temp regs die before the 42-reg buffer lives) ----
    float p[9];
#pragma unroll
    for (int k = 0; k < 9; k++)
        p[k] = sY[(ty + 3 + k / 3) * PITCH + (tx + 3 + k % 3)];

    ce(p[1], p[2]); ce(p[4], p[5]); ce(p[7], p[8]);
    ce(p[0], p[1]); ce(p[3], p[4]); ce(p[6], p[7]);
    ce(p[1], p[2]); ce(p[4], p[5]); ce(p[7], p[8]);
    ce(p[0], p[3]); ce(p[5], p[8]); ce(p[4], p[7]);
    ce(p[3], p[6]); ce(p[1], p[4]); ce(p[2], p[5]);
    ce(p[4], p[7]); ce(p[4], p[2]); ce(p[6], p[4]);
    ce(p[4], p[2]);
    float ylum = fminf(fmaxf(p[4], 0.0f), 1.0f);

    // ---- Chroma: exact 9x9 medians of U and V simultaneously (half2) ----
    __half2 uv = median81_h2(sUV, ty * PITCH + tx);
    float u = __low2float(uv);
    float v = __high2float(uv);

    // ---- YUV -> RGB ----
    float R = ylum + 1.13983f * v;
    float G = ylum - 0.39465f * u - 0.5806f * v;
    float B = ylum + 2.03211f * u;

    const int gy = by + ty;
    const int gx = bx + tx;
    size_t o = (size_t)bat * 3 * IMH * IMW + (size_t)gy * IMW + gx;
    out[o] = R;
    out[o + IMH * IMW] = G;
    out[o + 2 * IMH * IMW] = B;
}

extern "C" void kernel_launch(void* const* d_in, const int* in_sizes, int n_in,
                              void* d_out, int out_size) {
    const float* img = (const float*)d_in[0];
    float* out = (float*)d_out;
    int batch = in_sizes[0] / (3 * IMH * IMW);
    dim3 grid(IMW / TX, IMH / TY, batch);
    denoise_median_kernel<<<grid, 256>>>(img, out);
}

// round 4
// speedup vs baseline: 37.1839x; 2.6633x over previous
#include <cuda_runtime.h>
#include <cuda_fp16.h>

#define IMH 512
#define IMW 512
#define TX 32
#define TY 8
#define PITCH 41            // 40 halo-padded columns + 1 pad
#define NROWS 16            // TY + 8
#define PLANE (PITCH * NROWS)

__device__ __forceinline__ void ce(float& a, float& b) {
    float lo = fminf(a, b);
    float hi = fmaxf(a, b);
    a = lo;
    b = hi;
}

__device__ __forceinline__ void ce2(__half2& a, __half2& b) {
    __half2 lo = __hmin2(a, b);
    __half2 hi = __hmax2(a, b);
    a = lo;
    b = hi;
}

// Ascending bitonic merge stages over t[0..L) with virtual +inf padding to the
// next power of two: comparators reaching index >= L are no-ops and skipped.
// Input must be bitonic under that padding: [descending | ascending | +inf...].
template <int L, int S>
__device__ __forceinline__ void bstages(__half2 (&t)[L]) {
    if constexpr (S >= 1) {
#pragma unroll
        for (int i = 0; i + S < L; i++)
            if ((i & S) == 0) ce2(t[i], t[i + S]);
        bstages<L, S / 2>(t);
    }
}

// Odd-even transposition sort of 9 (36 CEs, trivially correct).
__device__ __forceinline__ void sort9(__half2 (&v)[9]) {
#pragma unroll
    for (int r = 0; r < 9; r++) {
#pragma unroll
        for (int i = (r & 1); i + 1 < 9; i += 2) ce2(v[i], v[i + 1]);
    }
}

__device__ __forceinline__ int reflect_idx(int i, int n) {
    if (i < 0) i = -1 - i;          // numpy 'symmetric' padding
    if (i >= n) i = 2 * n - 1 - i;
    return i;
}

__global__ void __launch_bounds__(256, 2)
denoise_median_kernel(const float* __restrict__ img, float* __restrict__ out) {
    __shared__ float sY[PLANE];
    __shared__ __half2 sUV[PLANE];
    __shared__ __half2 sCol[8 * 40 * 9];   // [rowgroup][tilecol][rank]

    const int bx = blockIdx.x * TX;
    const int by = blockIdx.y * TY;
    const int bat = blockIdx.z;
    const int tid = threadIdx.x;

    const float* Rp = img + (size_t)bat * 3 * IMH * IMW;
    const float* Gp = Rp + IMH * IMW;
    const float* Bp = Gp + IMH * IMW;

    // ---- Phase 1: load halo tile (40 x 16), RGB->YUV on the fly ----
    for (int idx = tid; idx < NROWS * 40; idx += 256) {
        int r = idx / 40;
        int c = idx % 40;
        int gy = reflect_idx(by - 4 + r, IMH);
        int gx = reflect_idx(bx - 4 + c, IMW);
        float R = Rp[gy * IMW + gx];
        float G = Gp[gy * IMW + gx];
        float B = Bp[gy * IMW + gx];
        float Y = 0.299f * R + 0.587f * G + 0.114f * B;
        float U = -0.14713f * R - 0.28886f * G + 0.436f * B;
        float V = 0.615f * R - 0.51499f * G - 0.10001f * B;
        sY[r * PITCH + c] = Y;
        sUV[r * PITCH + c] = __floats2half2_rn(U, V);
    }
    __syncthreads();

    // ---- Phase 2: sorted 9-columns, shared by 9 adjacent windows each ----
    // 8 row-groups x 40 tile columns = 320 column sorts.
    for (int idx = tid; idx < 8 * 40; idx += 256) {
        int rg = idx / 40;
        int c = idx % 40;
        __half2 v[9];
#pragma unroll
        for (int k = 0; k < 9; k++) v[k] = sUV[(rg + k) * PITCH + c];
        sort9(v);
#pragma unroll
        for (int k = 0; k < 9; k++) sCol[idx * 9 + k] = v[k];
    }
    __syncthreads();

    const int tx = tid & 31;
    const int ty = tid >> 5;

    // ---- Luma: 3x3 median (19-CE network, fp32), clip to [0,1] ----
    float p[9];
#pragma unroll
    for (int k = 0; k < 9; k++)
        p[k] = sY[(ty + 3 + k / 3) * PITCH + (tx + 3 + k % 3)];

    ce(p[1], p[2]); ce(p[4], p[5]); ce(p[7], p[8]);
    ce(p[0], p[1]); ce(p[3], p[4]); ce(p[6], p[7]);
    ce(p[1], p[2]); ce(p[4], p[5]); ce(p[7], p[8]);
    ce(p[0], p[3]); ce(p[5], p[8]); ce(p[4], p[7]);
    ce(p[3], p[6]); ce(p[1], p[4]); ce(p[2], p[5]);
    ce(p[4], p[7]); ce(p[4], p[2]); ce(p[6], p[4]);
    ce(p[4], p[2]);
    float ylum = fminf(fmaxf(p[4], 0.0f), 1.0f);

    // ---- Chroma: exact 9x9 median via sorted-column merge tree ----
    const int cb = (ty * 40 + tx) * 9;   // sorted column base for dj=0

    // Merge columns 0..3 -> A[36] ascending
    __half2 A[36];
    {
        __half2 r0[18], r1[18];
#pragma unroll
        for (int k = 0; k < 9; k++) {
            r0[k] = sCol[cb + 0 * 9 + (8 - k)];     // col0 descending
            r0[9 + k] = sCol[cb + 1 * 9 + k];       // col1 ascending
            r1[k] = sCol[cb + 2 * 9 + (8 - k)];
            r1[9 + k] = sCol[cb + 3 * 9 + k];
        }
        bstages<18, 16>(r0);
        bstages<18, 16>(r1);
#pragma unroll
        for (int k = 0; k < 18; k++) {
            A[k] = r0[17 - k];                       // descending half
            A[18 + k] = r1[k];                       // ascending half
        }
        bstages<36, 32>(A);
    }

    // Merge columns 4..7 -> B[36] ascending
    __half2 B36[36];
    {
        __half2 r0[18], r1[18];
#pragma unroll
        for (int k = 0; k < 9; k++) {
            r0[k] = sCol[cb + 4 * 9 + (8 - k)];
            r0[9 + k] = sCol[cb + 5 * 9 + k];
            r1[k] = sCol[cb + 6 * 9 + (8 - k)];
            r1[9 + k] = sCol[cb + 7 * 9 + k];
        }
        bstages<18, 16>(r0);
        bstages<18, 16>(r1);
#pragma unroll
        for (int k = 0; k < 18; k++) {
            B36[k] = r0[17 - k];
            B36[18 + k] = r1[k];
        }
        bstages<36, 32>(B36);
    }

    // Merge A+B -> 72; only ranks 31..40 can be the global median
    // (the 9th column shifts rank by at most 9). DCE prunes the rest.
    __half2 T[72];
#pragma unroll
    for (int k = 0; k < 36; k++) {
        T[k] = A[35 - k];
        T[36 + k] = B36[k];
    }
    bstages<72, 64>(T);

    // Final: median = element 9 (0-based) of merge(T[31..40], col8[0..8]),
    // via merged[k] = max_{i+j=k} min(a[i], b[j])  (out-of-range => +inf).
    __half2 m = T[31];
#pragma unroll
    for (int k = 1; k <= 9; k++)
        m = __hmax2(m, __hmin2(T[31 + k], sCol[cb + 8 * 9 + (9 - k)]));

    float u = __low2float(m);
    float v = __high2float(m);

    // ---- YUV -> RGB ----
    float R = ylum + 1.13983f * v;
    float G = ylum - 0.39465f * u - 0.5806f * v;
    float B = ylum + 2.03211f * u;

    const int gy = by + ty;
    const int gx = bx + tx;
    size_t o = (size_t)bat * 3 * IMH * IMW + (size_t)gy * IMW + gx;
    out[o] = R;
    out[o + IMH * IMW] = G;
    out[o + 2 * IMH * IMW] = B;
}

extern "C" void kernel_launch(void* const* d_in, const int* in_sizes, int n_in,
                              void* d_out, int out_size) {
    const float* img = (const float*)d_in[0];
    float* out = (float*)d_out;
    int batch = in_sizes[0] / (3 * IMH * IMW);
    dim3 grid(IMW / TX, IMH / TY, batch);
    denoise_median_kernel<<<grid, 256>>>(img, out);
}

// round 5
// speedup vs baseline: 57.3186x; 1.5415x over previous
#include <cuda_runtime.h>
#include <cuda_fp16.h>

#define IMH 512
#define IMW 512
#define TW 64               // tile width in pixels (2 px per thread)
#define TY 8
#define NCOLS 72            // TW + 8 halo
#define PITCH 73            // 72 + 1 pad
#define NROWS 16            // TY + 8
#define PLANE (PITCH * NROWS)

__device__ __forceinline__ void ce(float& a, float& b) {
    float lo = fminf(a, b);
    float hi = fmaxf(a, b);
    a = lo;
    b = hi;
}

__device__ __forceinline__ void ce2(__half2& a, __half2& b) {
    __half2 lo = __hmin2(a, b);
    __half2 hi = __hmax2(a, b);
    a = lo;
    b = hi;
}

// Ascending bitonic merge stages over t[0..L) with virtual +inf padding to the
// next power of two: comparators reaching index >= L are skipped.
// Input must be bitonic: [descending | ascending | +inf...].
template <int L, int S>
__device__ __forceinline__ void bstages(__half2 (&t)[L]) {
    if constexpr (S >= 1) {
#pragma unroll
        for (int i = 0; i + S < L; i++)
            if ((i & S) == 0) ce2(t[i], t[i + S]);
        bstages<L, S / 2>(t);
    }
}

// Odd-even transposition sort of 9 (36 CEs).
__device__ __forceinline__ void sort9(__half2 (&v)[9]) {
#pragma unroll
    for (int r = 0; r < 9; r++) {
#pragma unroll
        for (int i = (r & 1); i + 1 < 9; i += 2) ce2(v[i], v[i + 1]);
    }
}

__device__ __forceinline__ int reflect_idx(int i, int n) {
    if (i < 0) i = -1 - i;          // numpy 'symmetric'
    if (i >= n) i = 2 * n - 1 - i;
    return i;
}

// fp32 3x3 median (19 CE) at halo-center column cc, rowgroup ty.
__device__ __forceinline__ float lum3x3(const float* sY, int ty, int cc) {
    float p[9];
#pragma unroll
    for (int k = 0; k < 9; k++)
        p[k] = sY[(ty + 3 + k / 3) * PITCH + (cc - 1 + k % 3)];
    ce(p[1], p[2]); ce(p[4], p[5]); ce(p[7], p[8]);
    ce(p[0], p[1]); ce(p[3], p[4]); ce(p[6], p[7]);
    ce(p[1], p[2]); ce(p[4], p[5]); ce(p[7], p[8]);
    ce(p[0], p[3]); ce(p[5], p[8]); ce(p[4], p[7]);
    ce(p[3], p[6]); ce(p[1], p[4]); ce(p[2], p[5]);
    ce(p[4], p[7]); ce(p[4], p[2]); ce(p[6], p[4]);
    ce(p[4], p[2]);
    return fminf(fmaxf(p[4], 0.0f), 1.0f);
}

__global__ void __launch_bounds__(256, 2)
denoise_median_kernel(const float* __restrict__ img, float* __restrict__ out) {
    __shared__ float sY[PLANE];
    __shared__ __half2 sUV[PLANE];
    __shared__ __half2 sCol[8 * NCOLS * 9];   // [rowgroup][halocol][rank]

    const int bx = blockIdx.x * TW;
    const int by = blockIdx.y * TY;
    const int bat = blockIdx.z;
    const int tid = threadIdx.x;

    const float* Rp = img + (size_t)bat * 3 * IMH * IMW;
    const float* Gp = Rp + IMH * IMW;
    const float* Bp = Gp + IMH * IMW;

    // ---- Phase 1: load halo tile (72 x 16), RGB->YUV on the fly ----
    for (int idx = tid; idx < NROWS * NCOLS; idx += 256) {
        int r = idx / NCOLS;
        int c = idx % NCOLS;
        int gy = reflect_idx(by - 4 + r, IMH);
        int gx = reflect_idx(bx - 4 + c, IMW);
        float R = Rp[gy * IMW + gx];
        float G = Gp[gy * IMW + gx];
        float B = Bp[gy * IMW + gx];
        sY[r * PITCH + c] = 0.299f * R + 0.587f * G + 0.114f * B;
        float U = -0.14713f * R - 0.28886f * G + 0.436f * B;
        float V = 0.615f * R - 0.51499f * G - 0.10001f * B;
        sUV[r * PITCH + c] = __floats2half2_rn(U, V);
    }
    __syncthreads();

    // ---- Phase 2: sorted 9-columns (shared across windows) ----
    for (int idx = tid; idx < 8 * NCOLS; idx += 256) {
        int rg = idx / NCOLS;
        int c = idx % NCOLS;
        __half2 v[9];
#pragma unroll
        for (int k = 0; k < 9; k++) v[k] = sUV[(rg + k) * PITCH + c];
        sort9(v);
#pragma unroll
        for (int k = 0; k < 9; k++) sCol[idx * 9 + k] = v[k];
    }
    __syncthreads();

    const int tx = tid & 31;
    const int ty = tid >> 5;
    const int c0 = 2 * tx;            // left pixel's local halo column base

    // ---- Shared merge of the 8 columns common to both pixels ----
    const int cb = (ty * NCOLS) * 9;  // rowgroup base in sCol
#define COLP(c, k) sCol[cb + (c) * 9 + (k)]

    __half2 A[36];
    {
        __half2 r0[18], r1[18];
#pragma unroll
        for (int k = 0; k < 9; k++) {
            r0[k]     = COLP(c0 + 1, 8 - k);
            r0[9 + k] = COLP(c0 + 2, k);
            r1[k]     = COLP(c0 + 3, 8 - k);
            r1[9 + k] = COLP(c0 + 4, k);
        }
        bstages<18, 16>(r0);
        bstages<18, 16>(r1);
#pragma unroll
        for (int k = 0; k < 18; k++) {
            A[k]      = r0[17 - k];
            A[18 + k] = r1[k];
        }
        bstages<36, 32>(A);
    }
    __half2 B36[36];
    {
        __half2 r0[18], r1[18];
#pragma unroll
        for (int k = 0; k < 9; k++) {
            r0[k]     = COLP(c0 + 5, 8 - k);
            r0[9 + k] = COLP(c0 + 6, k);
            r1[k]     = COLP(c0 + 7, 8 - k);
            r1[9 + k] = COLP(c0 + 8, k);
        }
        bstages<18, 16>(r0);
        bstages<18, 16>(r1);
#pragma unroll
        for (int k = 0; k < 18; k++) {
            B36[k]      = r0[17 - k];
            B36[18 + k] = r1[k];
        }
        bstages<36, 32>(B36);
    }

    __half2 T[72];
#pragma unroll
    for (int k = 0; k < 36; k++) {
        T[k]      = A[35 - k];
        T[36 + k] = B36[k];
    }
    bstages<72, 64>(T);   // only ranks 31..40 consumed -> DCE prunes cone

    // ---- Per-pixel: add private column via rank-40 selection identity ----
    // merged[40] = max_{i+j=40} min(T[i], col[j]), OOR -> +inf.
    __half2 mL = T[31], mR = T[31];
#pragma unroll
    for (int k = 1; k <= 9; k++) {
        mL = __hmax2(mL, __hmin2(T[31 + k], COLP(c0,     9 - k)));
        mR = __hmax2(mR, __hmin2(T[31 + k], COLP(c0 + 9, 9 - k)));
    }

    // ---- Luma: two fp32 3x3 medians ----
    float ylumL = lum3x3(sY, ty, c0 + 4);
    float ylumR = lum3x3(sY, ty, c0 + 5);

    // ---- YUV -> RGB, vectorized pair store ----
    float uL = __low2float(mL), vL = __high2float(mL);
    float uR = __low2float(mR), vR = __high2float(mR);

    float2 Rv = make_float2(ylumL + 1.13983f * vL, ylumR + 1.13983f * vR);
    float2 Gv = make_float2(ylumL - 0.39465f * uL - 0.5806f * vL,
                            ylumR - 0.39465f * uR - 0.5806f * vR);
    float2 Bv = make_float2(ylumL + 2.03211f * uL, ylumR + 2.03211f * uR);

    const int gy = by + ty;
    const int gx = bx + c0;
    size_t o = (size_t)bat * 3 * IMH * IMW + (size_t)gy * IMW + gx;
    *(float2*)(out + o) = Rv;
    *(float2*)(out + o + IMH * IMW) = Gv;
    *(float2*)(out + o + 2 * IMH * IMW) = Bv;
#undef COLP
}

extern "C" void kernel_launch(void* const* d_in, const int* in_sizes, int n_in,
                              void* d_out, int out_size) {
    const float* img = (const float*)d_in[0];
    float* out = (float*)d_out;
    int batch = in_sizes[0] / (3 * IMH * IMW);
    dim3 grid(IMW / TW, IMH / TY, batch);
    denoise_median_kernel<<<grid, 256>>>(img, out);
}

// round 6
// speedup vs baseline: 62.5054x; 1.0905x over previous
#include <cuda_runtime.h>
#include <cuda_fp16.h>

#define IMH 512
#define IMW 512
#define TW 64               // tile width in pixels (2 px per thread)
#define TY 8
#define NCOLS 72            // TW + 8 halo
#define PITCH 73            // 72 + 1 pad
#define NROWS 16            // TY + 8
#define PLANE (PITCH * NROWS)

__device__ __forceinline__ void ce(float& a, float& b) {
    float lo = fminf(a, b);
    float hi = fmaxf(a, b);
    a = lo;
    b = hi;
}

__device__ __forceinline__ void ce2(__half2& a, __half2& b) {
    __half2 lo = __hmin2(a, b);
    __half2 hi = __hmax2(a, b);
    a = lo;
    b = hi;
}

// Ascending bitonic merge stages over t[0..L) with virtual +inf padding to the
// next power of two: comparators reaching index >= L are skipped.
// Input must be bitonic: [descending | ascending | +inf...].
template <int L, int S>
__device__ __forceinline__ void bstages(__half2 (&t)[L]) {
    if constexpr (S >= 1) {
#pragma unroll
        for (int i = 0; i + S < L; i++)
            if ((i & S) == 0) ce2(t[i], t[i + S]);
        bstages<L, S / 2>(t);
    }
}

// Odd-even transposition sort of 9 (36 CEs).
__device__ __forceinline__ void sort9(__half2 (&v)[9]) {
#pragma unroll
    for (int r = 0; r < 9; r++) {
#pragma unroll
        for (int i = (r & 1); i + 1 < 9; i += 2) ce2(v[i], v[i + 1]);
    }
}

__device__ __forceinline__ int reflect_idx(int i, int n) {
    if (i < 0) i = -1 - i;          // numpy 'symmetric'
    if (i >= n) i = 2 * n - 1 - i;
    return i;
}

// fp32 3x3 median (19 CE) at halo-center column cc, rowgroup ty.
__device__ __forceinline__ float lum3x3(const float* sY, int ty, int cc) {
    float p[9];
#pragma unroll
    for (int k = 0; k < 9; k++)
        p[k] = sY[(ty + 3 + k / 3) * PITCH + (cc - 1 + k % 3)];
    ce(p[1], p[2]); ce(p[4], p[5]); ce(p[7], p[8]);
    ce(p[0], p[1]); ce(p[3], p[4]); ce(p[6], p[7]);
    ce(p[1], p[2]); ce(p[4], p[5]); ce(p[7], p[8]);
    ce(p[0], p[3]); ce(p[5], p[8]); ce(p[4], p[7]);
    ce(p[3], p[6]); ce(p[1], p[4]); ce(p[2], p[5]);
    ce(p[4], p[7]); ce(p[4], p[2]); ce(p[6], p[4]);
    ce(p[4], p[2]);
    return fminf(fmaxf(p[4], 0.0f), 1.0f);
}

__global__ void __launch_bounds__(256, 3)
denoise_median_kernel(const float* __restrict__ img, float* __restrict__ out) {
    __shared__ float sY[PLANE];
    __shared__ __half2 sUV[PLANE];
    __shared__ __half2 sCol[8 * NCOLS * 9];   // [rowgroup][halocol][rank]

    const int bx = blockIdx.x * TW;
    const int by = blockIdx.y * TY;
    const int bat = blockIdx.z;
    const int tid = threadIdx.x;

    const float* Rp = img + (size_t)bat * 3 * IMH * IMW;
    const float* Gp = Rp + IMH * IMW;
    const float* Bp = Gp + IMH * IMW;

    // ---- Phase 1: load halo tile (72 x 16), RGB->YUV on the fly ----
    for (int idx = tid; idx < NROWS * NCOLS; idx += 256) {
        int r = idx / NCOLS;
        int c = idx % NCOLS;
        int gy = reflect_idx(by - 4 + r, IMH);
        int gx = reflect_idx(bx - 4 + c, IMW);
        float R = Rp[gy * IMW + gx];
        float G = Gp[gy * IMW + gx];
        float B = Bp[gy * IMW + gx];
        sY[r * PITCH + c] = 0.299f * R + 0.587f * G + 0.114f * B;
        float U = -0.14713f * R - 0.28886f * G + 0.436f * B;
        float V = 0.615f * R - 0.51499f * G - 0.10001f * B;
        sUV[r * PITCH + c] = __floats2half2_rn(U, V);
    }
    __syncthreads();

    // ---- Phase 2: sorted 9-columns (shared across windows) ----
    for (int idx = tid; idx < 8 * NCOLS; idx += 256) {
        int rg = idx / NCOLS;
        int c = idx % NCOLS;
        __half2 v[9];
#pragma unroll
        for (int k = 0; k < 9; k++) v[k] = sUV[(rg + k) * PITCH + c];
        sort9(v);
#pragma unroll
        for (int k = 0; k < 9; k++) sCol[idx * 9 + k] = v[k];
    }
    __syncthreads();

    const int tx = tid & 31;
    const int ty = tid >> 5;
    const int c0 = 2 * tx;            // left pixel's local halo column base

    // ---- Luma first: only 2 scalars stay live across the big merge ----
    float ylumL = lum3x3(sY, ty, c0 + 4);
    float ylumR = lum3x3(sY, ty, c0 + 5);

    // ---- Shared merge of the 8 columns common to both pixels ----
    const int cb = (ty * NCOLS) * 9;  // rowgroup base in sCol
#define COLP(c, k) sCol[cb + (c) * 9 + (k)]

    __half2 A[36];
    {
        __half2 r0[18], r1[18];
#pragma unroll
        for (int k = 0; k < 9; k++) {
            r0[k]     = COLP(c0 + 1, 8 - k);
            r0[9 + k] = COLP(c0 + 2, k);
            r1[k]     = COLP(c0 + 3, 8 - k);
            r1[9 + k] = COLP(c0 + 4, k);
        }
        bstages<18, 16>(r0);
        bstages<18, 16>(r1);
#pragma unroll
        for (int k = 0; k < 18; k++) {
            A[k]      = r0[17 - k];
            A[18 + k] = r1[k];
        }
        bstages<36, 32>(A);
    }
    __half2 B36[36];
    {
        __half2 r0[18], r1[18];
#pragma unroll
        for (int k = 0; k < 9; k++) {
            r0[k]     = COLP(c0 + 5, 8 - k);
            r0[9 + k] = COLP(c0 + 6, k);
            r1[k]     = COLP(c0 + 7, 8 - k);
            r1[9 + k] = COLP(c0 + 8, k);
        }
        bstages<18, 16>(r0);
        bstages<18, 16>(r1);
#pragma unroll
        for (int k = 0; k < 18; k++) {
            B36[k]      = r0[17 - k];
            B36[18 + k] = r1[k];
        }
        bstages<36, 32>(B36);
    }

    __half2 T[72];
#pragma unroll
    for (int k = 0; k < 36; k++) {
        T[k]      = A[35 - k];
        T[36 + k] = B36[k];
    }
    bstages<72, 64>(T);   // only ranks 31..40 consumed -> DCE prunes cone

    // ---- Per-pixel: add private column via rank-40 selection identity ----
    // merged[40] = max_{i+j=40} min(T[i], col[j]), OOR -> +inf.
    __half2 mL = T[31], mR = T[31];
#pragma unroll
    for (int k = 1; k <= 9; k++) {
        mL = __hmax2(mL, __hmin2(T[31 + k], COLP(c0,     9 - k)));
        mR = __hmax2(mR, __hmin2(T[31 + k], COLP(c0 + 9, 9 - k)));
    }

    // ---- YUV -> RGB, vectorized pair store ----
    float uL = __low2float(mL), vL = __high2float(mL);
    float uR = __low2float(mR), vR = __high2float(mR);

    float2 Rv = make_float2(ylumL + 1.13983f * vL, ylumR + 1.13983f * vR);
    float2 Gv = make_float2(ylumL - 0.39465f * uL - 0.5806f * vL,
                            ylumR - 0.39465f * uR - 0.5806f * vR);
    float2 Bv = make_float2(ylumL + 2.03211f * uL, ylumR + 2.03211f * uR);

    const int gy = by + ty;
    const int gx = bx + c0;
    size_t o = (size_t)bat * 3 * IMH * IMW + (size_t)gy * IMW + gx;
    *(float2*)(out + o) = Rv;
    *(float2*)(out + o + IMH * IMW) = Gv;
    *(float2*)(out + o + 2 * IMH * IMW) = Bv;
#undef COLP
}

extern "C" void kernel_launch(void* const* d_in, const int* in_sizes, int n_in,
                              void* d_out, int out_size) {
    const float* img = (const float*)d_in[0];
    float* out = (float*)d_out;
    int batch = in_sizes[0] / (3 * IMH * IMW);
    dim3 grid(IMW / TW, IMH / TY, batch);
    denoise_median_kernel<<<grid, 256>>>(img, out);
}

// round 7
// speedup vs baseline: 71.8123x; 1.1489x over previous
#include <cuda_runtime.h>
#include <cuda_fp16.h>

#define IMH 512
#define IMW 512
#define TW 64               // tile width in pixels (2 px per thread)
#define TY 8
#define NCOLS 72            // TW + 8 halo
#define PITCH 73            // 72 + 1 pad
#define NROWS 16            // TY + 8
#define PLANE (PITCH * NROWS)
#define NGRP 34             // odd-start 4-column groups per rowgroup
#define GSTRIDE 37          // padded group stride (half2) -> conflict-free

// smem layout (bytes)
#define OFF_Y    0
#define OFF_UV   2368                       // PLANE*2 = 2336, pad to 2368
#define OFF_COL  (OFF_UV + PLANE * 4 + 32)  // 7072
#define OFF_GRP  (OFF_COL + 8 * NCOLS * 9 * 4 + 32)
#define SMEM_TOTAL (OFF_GRP + 8 * NGRP * GSTRIDE * 4)

__device__ __forceinline__ void ce2(__half2& a, __half2& b) {
    __half2 lo = __hmin2(a, b);
    __half2 hi = __hmax2(a, b);
    a = lo;
    b = hi;
}

// Ascending bitonic merge stages over t[0..L) with virtual +inf padding to the
// next power of two: comparators reaching index >= L are skipped.
// Input must be bitonic: [descending | ascending | +inf...].
template <int L, int S>
__device__ __forceinline__ void bstages(__half2 (&t)[L]) {
    if constexpr (S >= 1) {
#pragma unroll
        for (int i = 0; i + S < L; i++)
            if ((i & S) == 0) ce2(t[i], t[i + S]);
        bstages<L, S / 2>(t);
    }
}

// Odd-even transposition sort of 9 (36 CEs, provably correct).
__device__ __forceinline__ void sort9(__half2 (&v)[9]) {
#pragma unroll
    for (int r = 0; r < 9; r++) {
#pragma unroll
        for (int i = (r & 1); i + 1 < 9; i += 2) ce2(v[i], v[i + 1]);
    }
}

__device__ __forceinline__ int reflect_idx(int i, int n) {
    if (i < 0) i = -1 - i;          // numpy 'symmetric'
    if (i >= n) i = 2 * n - 1 - i;
    return i;
}

__global__ void __launch_bounds__(256, 3)
denoise_median_kernel(const float* __restrict__ img, float* __restrict__ out) {
    extern __shared__ char smem_raw[];
    __half*  sYh  = (__half*)(smem_raw + OFF_Y);     // luma, fp16
    __half2* sUV  = (__half2*)(smem_raw + OFF_UV);   // (U,V) packed
    __half2* sCol = (__half2*)(smem_raw + OFF_COL);  // sorted 9-columns
    __half2* sGrp = (__half2*)(smem_raw + OFF_GRP);  // sorted 4-col groups (36)

    const int bx = blockIdx.x * TW;
    const int by = blockIdx.y * TY;
    const int bat = blockIdx.z;
    const int tid = threadIdx.x;

    const float* Rp = img + (size_t)bat * 3 * IMH * IMW;
    const float* Gp = Rp + IMH * IMW;
    const float* Bp = Gp + IMH * IMW;

    // ---- Phase 1: load halo tile (72 x 16), RGB->YUV on the fly ----
    for (int idx = tid; idx < NROWS * NCOLS; idx += 256) {
        int r = idx / NCOLS;
        int c = idx % NCOLS;
        int gy = reflect_idx(by - 4 + r, IMH);
        int gx = reflect_idx(bx - 4 + c, IMW);
        float R = Rp[gy * IMW + gx];
        float G = Gp[gy * IMW + gx];
        float B = Bp[gy * IMW + gx];
        float Y = 0.299f * R + 0.587f * G + 0.114f * B;
        float U = -0.14713f * R - 0.28886f * G + 0.436f * B;
        float V = 0.615f * R - 0.51499f * G - 0.10001f * B;
        sYh[r * PITCH + c] = __float2half(Y);
        sUV[r * PITCH + c] = __floats2half2_rn(U, V);
    }
    __syncthreads();

    // ---- Phase 2: sorted 9-columns (shared across windows) ----
    for (int idx = tid; idx < 8 * NCOLS; idx += 256) {
        int rg = idx / NCOLS;
        int c = idx % NCOLS;
        __half2 v[9];
#pragma unroll
        for (int k = 0; k < 9; k++) v[k] = sUV[(rg + k) * PITCH + c];
        sort9(v);
#pragma unroll
        for (int k = 0; k < 9; k++) sCol[idx * 9 + k] = v[k];
    }
    __syncthreads();

    // ---- Phase 2.5: sorted-36 groups of 4 columns, built ONCE each ----
    // Group g (start col s=2g+1) is A for thread c0=s-1 and B for c0=s-5.
    for (int idx = tid; idx < 8 * NGRP; idx += 256) {
        int rg = idx / NGRP;
        int g = idx % NGRP;
        int s = 2 * g + 1;
        const int cbase = (rg * NCOLS) * 9;
        __half2 r0[18], r1[18];
#pragma unroll
        for (int k = 0; k < 9; k++) {
            r0[k]     = sCol[cbase + (s + 0) * 9 + (8 - k)];  // desc
            r0[9 + k] = sCol[cbase + (s + 1) * 9 + k];        // asc
            r1[k]     = sCol[cbase + (s + 2) * 9 + (8 - k)];
            r1[9 + k] = sCol[cbase + (s + 3) * 9 + k];
        }
        bstages<18, 16>(r0);
        bstages<18, 16>(r1);
        __half2 A[36];
#pragma unroll
        for (int k = 0; k < 18; k++) {
            A[k]      = r0[17 - k];
            A[18 + k] = r1[k];
        }
        bstages<36, 32>(A);
        __half2* dst = sGrp + (rg * NGRP + g) * GSTRIDE;
#pragma unroll
        for (int k = 0; k < 36; k++) dst[k] = A[k];
    }
    __syncthreads();

    const int tx = tid & 31;
    const int ty = tid >> 5;
    const int c0 = 2 * tx;            // left pixel's local halo column base

    // ---- Luma: both pixels' 3x3 medians in one half2 network ----
    __half2 pl[9];
#pragma unroll
    for (int k = 0; k < 9; k++) {
        int r = ty + 3 + k / 3;
        int c = c0 + 3 + k % 3;
        pl[k] = __halves2half2(sYh[r * PITCH + c], sYh[r * PITCH + c + 1]);
    }
    ce2(pl[1], pl[2]); ce2(pl[4], pl[5]); ce2(pl[7], pl[8]);
    ce2(pl[0], pl[1]); ce2(pl[3], pl[4]); ce2(pl[6], pl[7]);
    ce2(pl[1], pl[2]); ce2(pl[4], pl[5]); ce2(pl[7], pl[8]);
    ce2(pl[0], pl[3]); ce2(pl[5], pl[8]); ce2(pl[4], pl[7]);
    ce2(pl[3], pl[6]); ce2(pl[1], pl[4]); ce2(pl[2], pl[5]);
    ce2(pl[4], pl[7]); ce2(pl[4], pl[2]); ce2(pl[6], pl[4]);
    ce2(pl[4], pl[2]);
    __half2 ylum2 = __hmin2(__hmax2(pl[4], __floats2half2_rn(0.f, 0.f)),
                            __floats2half2_rn(1.f, 1.f));
    float ylumL = __low2float(ylum2);
    float ylumR = __high2float(ylum2);

    // ---- Chroma: load shared groups, pruned 72-merge ----
    const __half2* gA = sGrp + (ty * NGRP + tx) * GSTRIDE;      // cols c0+1..c0+4
    const __half2* gB = sGrp + (ty * NGRP + tx + 2) * GSTRIDE;  // cols c0+5..c0+8

    __half2 T[72];
#pragma unroll
    for (int k = 0; k < 36; k++) T[k] = gA[35 - k];   // descending half
#pragma unroll
    for (int k = 0; k < 36; k++) T[36 + k] = gB[k];   // ascending half
    bstages<72, 64>(T);   // only ranks 31..40 consumed -> DCE prunes cone

    // ---- Per-pixel: add private column via rank-40 selection identity ----
    // merged[40] = max_{i+j=40} min(T[i], col[j]), OOR -> +inf.
    const int cb = (ty * NCOLS) * 9;
    const __half2* colL = sCol + cb + c0 * 9;
    const __half2* colR = sCol + cb + (c0 + 9) * 9;
    __half2 mL = T[31], mR = T[31];
#pragma unroll
    for (int k = 1; k <= 9; k++) {
        mL = __hmax2(mL, __hmin2(T[31 + k], colL[9 - k]));
        mR = __hmax2(mR, __hmin2(T[31 + k], colR[9 - k]));
    }

    // ---- YUV -> RGB, vectorized pair store ----
    float uL = __low2float(mL), vL = __high2float(mL);
    float uR = __low2float(mR), vR = __high2float(mR);

    float2 Rv = make_float2(ylumL + 1.13983f * vL, ylumR + 1.13983f * vR);
    float2 Gv = make_float2(ylumL - 0.39465f * uL - 0.5806f * vL,
                            ylumR - 0.39465f * uR - 0.5806f * vR);
    float2 Bv = make_float2(ylumL + 2.03211f * uL, ylumR + 2.03211f * uR);

    const int gy = by + ty;
    const int gx = bx + c0;
    size_t o = (size_t)bat * 3 * IMH * IMW + (size_t)gy * IMW + gx;
    *(float2*)(out + o) = Rv;
    *(float2*)(out + o + IMH * IMW) = Gv;
    *(float2*)(out + o + 2 * IMH * IMW) = Bv;
}

extern "C" void kernel_launch(void* const* d_in, const int* in_sizes, int n_in,
                              void* d_out, int out_size) {
    const float* img = (const float*)d_in[0];
    float* out = (float*)d_out;
    int batch = in_sizes[0] / (3 * IMH * IMW);
    cudaFuncSetAttribute(denoise_median_kernel,
                         cudaFuncAttributeMaxDynamicSharedMemorySize, SMEM_TOTAL);
    dim3 grid(IMW / TW, IMH / TY, batch);
    denoise_median_kernel<<<grid, 256, SMEM_TOTAL>>>(img, out);
}

// round 8
// speedup vs baseline: 73.8957x; 1.0290x over previous
#include <cuda_runtime.h>
#include <cuda_fp16.h>

#define IMH 512
#define IMW 512
#define TW 128              // tile width (2 px per thread, 64 pairs/rowgroup)
#define TY 8
#define NCOLS 136           // TW + 8 halo
#define PITCH 137           // NCOLS + 1
#define NROWS 16            // TY + 8
#define NGRP 66             // odd-start 4-column groups per rowgroup
#define NCOLSORT (8 * NCOLS)   // 1088 column sorts per block
#define NGRPTOT  (8 * NGRP)    // 528 group builds per block

// smem layout (bytes): [sCol 39168][sY 4384 | sUV 8768] with sGrp (76032)
// overlapping the sY/sUV region (both dead before sGrp is written).
#define OFF_Y    39168
#define OFF_UV   (OFF_Y + PITCH * NROWS * 2)     // 43552
#define OFF_GRP  39168
#define SMEM_TOTAL (39168 + 36 * NGRPTOT * 4)    // 115200

__device__ __forceinline__ void ce2(__half2& a, __half2& b) {
    __half2 lo = __hmin2(a, b);
    __half2 hi = __hmax2(a, b);
    a = lo;
    b = hi;
}

// Ascending bitonic merge stages over t[0..L) with virtual +inf padding to the
// next power of two. Input must be bitonic: [descending | ascending | +inf...].
template <int L, int S>
__device__ __forceinline__ void bstages(__half2 (&t)[L]) {
    if constexpr (S >= 1) {
#pragma unroll
        for (int i = 0; i + S < L; i++)
            if ((i & S) == 0) ce2(t[i], t[i + S]);
        bstages<L, S / 2>(t);
    }
}

// sort9 in 29 CEs from verified primitives: 3x sort3, merge(3,3)->6, merge(6,3)->9.
__device__ __forceinline__ void sort9(__half2 (&v)[9]) {
#pragma unroll
    for (int b = 0; b < 9; b += 3) {
        ce2(v[b], v[b + 1]); ce2(v[b + 1], v[b + 2]); ce2(v[b], v[b + 1]);
    }
    __half2 m[6] = {v[2], v[1], v[0], v[3], v[4], v[5]};   // [desc3 | asc3]
    bstages<6, 4>(m);
    __half2 t[9] = {m[5], m[4], m[3], m[2], m[1], m[0],    // [desc6 | asc3]
                    v[6], v[7], v[8]};
    bstages<9, 8>(t);
#pragma unroll
    for (int k = 0; k < 9; k++) v[k] = t[k];
}

__device__ __forceinline__ int reflect_idx(int i, int n) {
    if (i < 0) i = -1 - i;          // numpy 'symmetric'
    if (i >= n) i = 2 * n - 1 - i;
    return i;
}

__global__ void __launch_bounds__(512, 2)
denoise_median_kernel(const float* __restrict__ img, float* __restrict__ out) {
    extern __shared__ char smem_raw[];
    __half2* sColT = (__half2*)smem_raw;                 // [rank][rg*136+col]
    __half*  sYh   = (__half*)(smem_raw + OFF_Y);        // luma fp16
    __half2* sUV   = (__half2*)(smem_raw + OFF_UV);      // (U,V) packed
    __half2* sGrpT = (__half2*)(smem_raw + OFF_GRP);     // [rank][rg*66+g]

    const int bx = blockIdx.x * TW;
    const int by = blockIdx.y * TY;
    const int bat = blockIdx.z;
    const int tid = threadIdx.x;

    const float* Rp = img + (size_t)bat * 3 * IMH * IMW;
    const float* Gp = Rp + IMH * IMW;
    const float* Bp = Gp + IMH * IMW;

    // ---- Phase 1: load halo tile (136 x 16), RGB->YUV on the fly ----
    for (int idx = tid; idx < NROWS * NCOLS; idx += 512) {
        int r = idx / NCOLS;
        int c = idx % NCOLS;
        int gy = reflect_idx(by - 4 + r, IMH);
        int gx = reflect_idx(bx - 4 + c, IMW);
        float R = Rp[gy * IMW + gx];
        float G = Gp[gy * IMW + gx];
        float B = Bp[gy * IMW + gx];
        float Y = 0.299f * R + 0.587f * G + 0.114f * B;
        float U = -0.14713f * R - 0.28886f * G + 0.436f * B;
        float V = 0.615f * R - 0.51499f * G - 0.10001f * B;
        sYh[r * PITCH + c] = __float2half(Y);
        sUV[r * PITCH + c] = __floats2half2_rn(U, V);
    }
    __syncthreads();

    const int tp = tid & 63;          // pixel-pair index within rowgroup
    const int ty = tid >> 6;          // rowgroup
    const int c0 = 2 * tp;            // left pixel's local halo column

    // ---- Phase 2a: luma (both pixels, one half2 3x3 network) -> registers ----
    __half2 pl[9];
#pragma unroll
    for (int k = 0; k < 9; k++) {
        int r = ty + 3 + k / 3;
        int c = c0 + 3 + k % 3;
        pl[k] = __halves2half2(sYh[r * PITCH + c], sYh[r * PITCH + c + 1]);
    }
    ce2(pl[1], pl[2]); ce2(pl[4], pl[5]); ce2(pl[7], pl[8]);
    ce2(pl[0], pl[1]); ce2(pl[3], pl[4]); ce2(pl[6], pl[7]);
    ce2(pl[1], pl[2]); ce2(pl[4], pl[5]); ce2(pl[7], pl[8]);
    ce2(pl[0], pl[3]); ce2(pl[5], pl[8]); ce2(pl[4], pl[7]);
    ce2(pl[3], pl[6]); ce2(pl[1], pl[4]); ce2(pl[2], pl[5]);
    ce2(pl[4], pl[7]); ce2(pl[4], pl[2]); ce2(pl[6], pl[4]);
    ce2(pl[4], pl[2]);
    __half2 ylum2 = __hmin2(__hmax2(pl[4], __floats2half2_rn(0.f, 0.f)),
                            __floats2half2_rn(1.f, 1.f));

    // ---- Phase 2b: sorted 9-columns into transposed sCol ----
    for (int idx = tid; idx < NCOLSORT; idx += 512) {
        int rg = idx / NCOLS;
        int c = idx % NCOLS;
        __half2 v[9];
#pragma unroll
        for (int k = 0; k < 9; k++) v[k] = sUV[(rg + k) * PITCH + c];
        sort9(v);
#pragma unroll
        for (int k = 0; k < 9; k++) sColT[k * NCOLSORT + idx] = v[k];
    }
    __syncthreads();   // sY/sUV dead from here; sGrp may overwrite them

    // ---- Phase 2.5: sorted-36 groups of 4 columns, built ONCE each ----
    for (int idx = tid; idx < NGRPTOT; idx += 512) {
        int rg = idx / NGRP;
        int g = idx % NGRP;
        int s = 2 * g + 1;
        const int cbase = rg * NCOLS;
        __half2 r0[18], r1[18];
#pragma unroll
        for (int k = 0; k < 9; k++) {
            r0[k]     = sColT[(8 - k) * NCOLSORT + cbase + s + 0];  // desc
            r0[9 + k] = sColT[k * NCOLSORT + cbase + s + 1];        // asc
            r1[k]     = sColT[(8 - k) * NCOLSORT + cbase + s + 2];
            r1[9 + k] = sColT[k * NCOLSORT + cbase + s + 3];
        }
        bstages<18, 16>(r0);
        bstages<18, 16>(r1);
        __half2 A[36];
#pragma unroll
        for (int k = 0; k < 18; k++) {
            A[k]      = r0[17 - k];
            A[18 + k] = r1[k];
        }
        bstages<36, 32>(A);
#pragma unroll
        for (int k = 0; k < 36; k++) sGrpT[k * NGRPTOT + idx] = A[k];
    }
    __syncthreads();

    // ---- Phase 3: pruned 72-merge of the two shared groups ----
    const int gAi = ty * NGRP + tp;       // cols c0+1..c0+4
    const int gBi = gAi + 2;              // cols c0+5..c0+8

    __half2 T[72];
#pragma unroll
    for (int k = 0; k < 36; k++) T[k] = sGrpT[(35 - k) * NGRPTOT + gAi];
#pragma unroll
    for (int k = 0; k < 36; k++) T[36 + k] = sGrpT[k * NGRPTOT + gBi];
    bstages<72, 64>(T);   // only ranks 31..40 consumed -> DCE prunes cone

    // ---- Per-pixel: add private column via rank-40 selection identity ----
    // merged[40] = max_{i+j=40} min(T[i], col[j]), OOR -> +inf.
    const int cbase = ty * NCOLS;
    __half2 mL = T[31], mR = T[31];
#pragma unroll
    for (int k = 1; k <= 9; k++) {
        mL = __hmax2(mL, __hmin2(T[31 + k], sColT[(9 - k) * NCOLSORT + cbase + c0]));
        mR = __hmax2(mR, __hmin2(T[31 + k], sColT[(9 - k) * NCOLSORT + cbase + c0 + 9]));
    }

    // ---- YUV -> RGB, vectorized pair store ----
    float ylumL = __low2float(ylum2);
    float ylumR = __high2float(ylum2);
    float uL = __low2float(mL), vL = __high2float(mL);
    float uR = __low2float(mR), vR = __high2float(mR);

    float2 Rv = make_float2(ylumL + 1.13983f * vL, ylumR + 1.13983f * vR);
    float2 Gv = make_float2(ylumL - 0.39465f * uL - 0.5806f * vL,
                            ylumR - 0.39465f * uR - 0.5806f * vR);
    float2 Bv = make_float2(ylumL + 2.03211f * uL, ylumR + 2.03211f * uR);

    const int gy = by + ty;
    const int gx = bx + c0;
    size_t o = (size_t)bat * 3 * IMH * IMW + (size_t)gy * IMW + gx;
    *(float2*)(out + o) = Rv;
    *(float2*)(out + o + IMH * IMW) = Gv;
    *(float2*)(out + o + 2 * IMH * IMW) = Bv;
}

extern "C" void kernel_launch(void* const* d_in, const int* in_sizes, int n_in,
                              void* d_out, int out_size) {
    const float* img = (const float*)d_in[0];
    float* out = (float*)d_out;
    int batch = in_sizes[0] / (3 * IMH * IMW);
    cudaFuncSetAttribute(denoise_median_kernel,
                         cudaFuncAttributeMaxDynamicSharedMemorySize, SMEM_TOTAL);
    dim3 grid(IMW / TW, IMH / TY, batch);
    denoise_median_kernel<<<grid, 512, SMEM_TOTAL>>>(img, out);
}